// round 15
// baseline (speedup 1.0000x reference)
#include <cuda_runtime.h>
#include <cuda_bf16.h>
#include <math.h>
#include <stdint.h>

#define MTOK   4096
#define WIDTH  1024
#define HEADS  16
#define HDIM   64
#define HIDDEN 4096
#define SEQ    2048

__device__ float g_h   [MTOK * WIDTH];
__device__ float g_qkv [MTOK * 3 * WIDTH];
__device__ float g_attn[MTOK * WIDTH];
__device__ float g_x1  [MTOK * WIDTH];
__device__ float g_fc1 [MTOK * HIDDEN];
__device__ float g_wqkv_r [WIDTH * 3 * WIDTH];
__device__ float g_wproj_r[WIDTH * WIDTH];
__device__ float g_wfc1_r [WIDTH * HIDDEN];
__device__ float g_wfc2_r [HIDDEN * WIDTH];

__device__ __forceinline__ float warp_sum(float v) {
    #pragma unroll
    for (int o = 16; o > 0; o >>= 1) v += __shfl_xor_sync(0xffffffffu, v, o);
    return v;
}

__device__ __forceinline__ float tf32r(float x) {
    uint32_t u;
    asm("cvt.rna.tf32.f32 %0, %1;" : "=r"(u) : "f"(x));
    return __uint_as_float(u);
}

__device__ __forceinline__ void mma_tf32(float c[4], const uint32_t a[4], const uint32_t b[2]) {
    asm volatile(
        "mma.sync.aligned.m16n8k8.row.col.f32.tf32.tf32.f32 "
        "{%0,%1,%2,%3}, {%4,%5,%6,%7}, {%8,%9}, {%0,%1,%2,%3};\n"
        : "+f"(c[0]), "+f"(c[1]), "+f"(c[2]), "+f"(c[3])
        : "r"(a[0]), "r"(a[1]), "r"(a[2]), "r"(a[3]),
          "r"(b[0]), "r"(b[1]));
}

__device__ __forceinline__ void cp_async16(uint32_t s, const void* g) {
    asm volatile("cp.async.cg.shared.global [%0], [%1], 16;\n" :: "r"(s), "l"(g));
}
__device__ __forceinline__ void cp_commit() {
    asm volatile("cp.async.commit_group;\n" ::: "memory");
}
template <int N>
__device__ __forceinline__ void cp_wait() {
    asm volatile("cp.async.wait_group %0;\n" :: "n"(N) : "memory");
}

__device__ __forceinline__ float gelu_exact(float x) {
    return 0.5f * x * (1.0f + erff(x * 0.7071067811865476f));
}

// ---------------------------------------------------------------------------
// Merged weight rounding
// ---------------------------------------------------------------------------
#define SEG0 786432
#define SEG1 1048576
#define SEG2 2097152
#define SEG3 3145728

__global__ void round_all_kernel(const float* __restrict__ wqkv,
                                 const float* __restrict__ wproj,
                                 const float* __restrict__ wfc1,
                                 const float* __restrict__ wfc2,
                                 float* __restrict__ oqkv,
                                 float* __restrict__ oproj,
                                 float* __restrict__ ofc1,
                                 float* __restrict__ ofc2) {
    int blk0 = blockIdx.x * 1024;
    const float4* in;
    float4* out;
    int off;
    if (blk0 < SEG0)      { in = (const float4*)wqkv;  out = (float4*)oqkv;  off = 0;    }
    else if (blk0 < SEG1) { in = (const float4*)wproj; out = (float4*)oproj; off = SEG0; }
    else if (blk0 < SEG2) { in = (const float4*)wfc1;  out = (float4*)ofc1;  off = SEG1; }
    else                  { in = (const float4*)wfc2;  out = (float4*)ofc2;  off = SEG2; }
    int base = blk0 - off + threadIdx.x;
    #pragma unroll
    for (int i = 0; i < 4; i++) {
        int idx = base + i * 256;
        float4 v = in[idx];
        out[idx] = make_float4(tf32r(v.x), tf32r(v.y), tf32r(v.z), tf32r(v.w));
    }
}

__global__ void ln_kernel(const float* __restrict__ x,
                          const float* __restrict__ g,
                          const float* __restrict__ b,
                          float* __restrict__ out) {
    int row = blockIdx.x;
    int t   = threadIdx.x;
    const float4* xr = reinterpret_cast<const float4*>(x + (size_t)row * WIDTH);
    float4 v = xr[t];
    float s  = v.x + v.y + v.z + v.w;
    float ss = v.x*v.x + v.y*v.y + v.z*v.z + v.w*v.w;

    __shared__ float red_s[8], red_ss[8];
    float ws = warp_sum(s), wss = warp_sum(ss);
    int wid = t >> 5, lid = t & 31;
    if (lid == 0) { red_s[wid] = ws; red_ss[wid] = wss; }
    __syncthreads();
    if (wid == 0) {
        float a  = (lid < 8) ? red_s[lid]  : 0.f;
        float a2 = (lid < 8) ? red_ss[lid] : 0.f;
        a  = warp_sum(a);
        a2 = warp_sum(a2);
        if (lid == 0) { red_s[0] = a; red_ss[0] = a2; }
    }
    __syncthreads();
    float mu  = red_s[0]  * (1.0f / WIDTH);
    float var = red_ss[0] * (1.0f / WIDTH) - mu * mu;
    float rs  = rsqrtf(var + 1e-5f);

    const float4* g4 = reinterpret_cast<const float4*>(g);
    const float4* b4 = reinterpret_cast<const float4*>(b);
    float4 gg = g4[t], bb = b4[t];
    float4 o;
    o.x = tf32r((v.x - mu) * rs * gg.x + bb.x);
    o.y = tf32r((v.y - mu) * rs * gg.y + bb.y);
    o.z = tf32r((v.z - mu) * rs * gg.z + bb.z);
    o.w = tf32r((v.w - mu) * rs * gg.w + bb.w);
    reinterpret_cast<float4*>(out + (size_t)row * WIDTH)[t] = o;
}

// ---------------------------------------------------------------------------
// TF32 tensor-core GEMM (proven R4/R9 config)
// ---------------------------------------------------------------------------
#define SA 36
#define SB 136
#define AS_FLOATS (128 * SA)
#define BS_FLOATS (32 * SB)
#define STAGE_FLOATS (AS_FLOATS + BS_FLOATS)
#define NSTAGE 3
#define GEMM_SMEM_BYTES (NSTAGE * STAGE_FLOATS * 4)

template <int OP, int ROUND_OUT>
__global__ void __launch_bounds__(256, 2)
gemm_tc(int M, int N, int K,
        const float* __restrict__ A,
        const float* __restrict__ B,
        const float* __restrict__ bias,
        const float* __restrict__ res,
        float* __restrict__ C) {
    extern __shared__ float sm[];

    const int tid     = threadIdx.x;
    const int warpId  = tid >> 5;
    const int lane    = tid & 31;
    const int gr      = lane >> 2;
    const int ctg     = lane & 3;
    const int warpRow = warpId >> 2;
    const int warpCol = warpId & 3;

    const int cRow = blockIdx.y;
    const int cCol = blockIdx.x;

    const float* Ablk = A + (size_t)cRow * 128 * K;
    const float* Bblk = B + cCol * 128;

    const uint32_t smBase = (uint32_t)__cvta_generic_to_shared(sm);

    auto load_stage = [&](int stg, int kb) {
        const uint32_t stageA = smBase + (uint32_t)(stg * STAGE_FLOATS) * 4u;
        const uint32_t stageB = stageA + (uint32_t)AS_FLOATS * 4u;
        const int kOff = kb << 5;
        #pragma unroll
        for (int i = 0; i < 4; i++) {
            int aIdx = tid + i * 256;
            int ar = aIdx >> 3, ac = (aIdx & 7) << 2;
            cp_async16(stageA + (uint32_t)(ar * SA + ac) * 4u,
                       Ablk + (size_t)ar * K + kOff + ac);
            int bIdx = tid + i * 256;
            int br = bIdx >> 5, bc = (bIdx & 31) << 2;
            cp_async16(stageB + (uint32_t)(br * SB + bc) * 4u,
                       Bblk + (size_t)(kOff + br) * N + bc);
        }
    };

    float acc[4][4][4];
    #pragma unroll
    for (int i = 0; i < 4; i++)
        #pragma unroll
        for (int j = 0; j < 4; j++)
            #pragma unroll
            for (int k = 0; k < 4; k++) acc[i][j][k] = 0.f;

    const int nChunk = K >> 5;

    load_stage(0, 0); cp_commit();
    load_stage(1, 1); cp_commit();
    cp_wait<1>();
    __syncthreads();

    for (int kb = 0; kb < nChunk; kb++) {
        const int cur = kb % NSTAGE;
        if (kb + 2 < nChunk) load_stage((kb + 2) % NSTAGE, kb + 2);
        cp_commit();

        const uint32_t* uAs = reinterpret_cast<const uint32_t*>(sm + cur * STAGE_FLOATS);
        const uint32_t* uBs = uAs + AS_FLOATS;

        #pragma unroll
        for (int ks = 0; ks < 4; ks++) {
            uint32_t af[4][4];
            #pragma unroll
            for (int mt = 0; mt < 4; mt++) {
                int m0 = warpRow * 64 + mt * 16 + gr;
                const uint32_t* pa = uAs + m0 * SA + ks * 8 + ctg;
                af[mt][0] = pa[0];
                af[mt][1] = pa[8 * SA];
                af[mt][2] = pa[4];
                af[mt][3] = pa[8 * SA + 4];
            }
            uint32_t bf[4][2];
            #pragma unroll
            for (int nt = 0; nt < 4; nt++) {
                int nb = warpCol * 32 + nt * 8 + gr;
                const uint32_t* pb = uBs + (ks * 8 + ctg) * SB + nb;
                bf[nt][0] = pb[0];
                bf[nt][1] = pb[4 * SB];
            }
            #pragma unroll
            for (int mt = 0; mt < 4; mt++)
                #pragma unroll
                for (int nt = 0; nt < 4; nt++)
                    mma_tf32(acc[mt][nt], af[mt], bf[nt]);
        }

        cp_wait<1>();
        __syncthreads();
    }

    #pragma unroll
    for (int mt = 0; mt < 4; mt++) {
        #pragma unroll
        for (int rr = 0; rr < 2; rr++) {
            const int row = cRow * 128 + warpRow * 64 + mt * 16 + gr + rr * 8;
            #pragma unroll
            for (int nt = 0; nt < 4; nt++) {
                const int col = cCol * 128 + warpCol * 32 + nt * 8 + 2 * ctg;
                float v0 = acc[mt][nt][rr * 2 + 0];
                float v1 = acc[mt][nt][rr * 2 + 1];
                if (OP == 1) {
                    float2 bi = *reinterpret_cast<const float2*>(bias + col);
                    float2 rv = *reinterpret_cast<const float2*>(res + (size_t)row * N + col);
                    v0 += bi.x + rv.x;
                    v1 += bi.y + rv.y;
                } else if (OP == 2) {
                    float2 bi = *reinterpret_cast<const float2*>(bias + col);
                    v0 = gelu_exact(v0 + bi.x);
                    v1 = gelu_exact(v1 + bi.y);
                }
                if (ROUND_OUT) { v0 = tf32r(v0); v1 = tf32r(v1); }
                *reinterpret_cast<float2*>(C + (size_t)row * N + col) = make_float2(v0, v1);
            }
        }
    }
}

// ---------------------------------------------------------------------------
// Flash attention: 16 query rows/warp (BQ=64, 4 warps, 128 threads) + shuffle
// P·V. Combines R10's low register pressure (-> 3 CTAs/SM, 12 warps) with
// R14's Ps-free P·V (no P smem roundtrip). smem = Ks+Vs only (34.8 KB).
// Q staged through Ks before the main loop; fragments live in registers.
// ---------------------------------------------------------------------------
#define SATT 68
#define KV_TILE (64 * SATT)
#define ATTN_SMEM_BYTES (2 * KV_TILE * 4)   // 34816

__global__ void __launch_bounds__(128)
attn_tc(const float* __restrict__ qkv, float* __restrict__ out) {
    extern __shared__ float sm[];
    float* Ks = sm;
    float* Vs = sm + KV_TILE;
    const uint32_t* uK = reinterpret_cast<const uint32_t*>(Ks);
    const uint32_t* uV = reinterpret_cast<const uint32_t*>(Vs);

    const int t     = threadIdx.x;
    const int warp  = t >> 5;
    const int lane  = t & 31;
    const int gr    = lane >> 2;
    const int ctg   = lane & 3;
    const int mbase = warp * 16;          // 16 query rows per warp

    const int qb = blockIdx.x;            // 0..31 (64-query blocks)
    const int bh = blockIdx.y;
    const int bb = bh >> 4;
    const int h  = bh & 15;
    const int tok0 = bb * SEQ;

    // shuffle source lanes for P-fragment gather (within quad group)
    const int loL = (lane & 28) | (ctg >> 1);   // gr*4 + (ctg>>1)
    const int hiL = loL + 2;
    const int sel = ctg & 1;

    // ---- stage Q (64x64) through Ks, extract fragments to regs ----
    #pragma unroll
    for (int i = 0; i < 8; i++) {
        int idx = t + i * 128;
        int row = idx >> 4;               // 0..63
        int c   = (idx & 15) << 2;
        *reinterpret_cast<float4*>(&Ks[row * SATT + c]) =
            *reinterpret_cast<const float4*>(
                qkv + (size_t)(tok0 + qb * 64 + row) * 3072 + h * 64 + c);
    }
    __syncthreads();
    uint32_t qf[8][4];
    #pragma unroll
    for (int ks = 0; ks < 8; ks++) {
        const uint32_t* pq = uK + (mbase + gr) * SATT + ks * 8 + ctg;
        qf[ks][0] = pq[0];
        qf[ks][1] = pq[8 * SATT];
        qf[ks][2] = pq[4];
        qf[ks][3] = pq[8 * SATT + 4];
    }
    // (loop-start __syncthreads orders extraction before Ks overwrite)

    float m0 = -1e30f, m1 = -1e30f, l0 = 0.f, l1 = 0.f;
    float o[8][4];
    #pragma unroll
    for (int nt = 0; nt < 8; nt++)
        #pragma unroll
        for (int k = 0; k < 4; k++) o[nt][k] = 0.f;

    for (int kb = 0; kb < SEQ / 64; kb++) {
        __syncthreads();

        // ---- load K, V tiles ----
        #pragma unroll
        for (int i = 0; i < 8; i++) {
            int idx = t + i * 128;
            int row = idx >> 4;
            int c   = (idx & 15) << 2;
            const float* base = qkv + (size_t)(tok0 + kb * 64 + row) * 3072 + h * 64 + c;
            *reinterpret_cast<float4*>(&Ks[row * SATT + c]) =
                *reinterpret_cast<const float4*>(base + 1024);
            *reinterpret_cast<float4*>(&Vs[row * SATT + c]) =
                *reinterpret_cast<const float4*>(base + 2048);
        }
        __syncthreads();

        // ---- S = Q K^T ----
        float s[8][4];
        #pragma unroll
        for (int nt = 0; nt < 8; nt++)
            #pragma unroll
            for (int k = 0; k < 4; k++) s[nt][k] = 0.f;

        #pragma unroll
        for (int ks = 0; ks < 8; ks++) {
            #pragma unroll
            for (int nt = 0; nt < 8; nt++) {
                uint32_t bf[2];
                const uint32_t* pb = uK + (nt * 8 + gr) * SATT + ks * 8 + ctg;
                bf[0] = pb[0];
                bf[1] = pb[4];
                mma_tf32(s[nt], qf[ks], bf);
            }
        }

        // ---- online softmax; round P in registers ----
        float mx0 = -1e30f, mx1 = -1e30f;
        #pragma unroll
        for (int nt = 0; nt < 8; nt++) {
            s[nt][0] *= 0.125f; s[nt][1] *= 0.125f;
            s[nt][2] *= 0.125f; s[nt][3] *= 0.125f;
            mx0 = fmaxf(mx0, fmaxf(s[nt][0], s[nt][1]));
            mx1 = fmaxf(mx1, fmaxf(s[nt][2], s[nt][3]));
        }
        mx0 = fmaxf(mx0, __shfl_xor_sync(0xffffffffu, mx0, 1));
        mx0 = fmaxf(mx0, __shfl_xor_sync(0xffffffffu, mx0, 2));
        mx1 = fmaxf(mx1, __shfl_xor_sync(0xffffffffu, mx1, 1));
        mx1 = fmaxf(mx1, __shfl_xor_sync(0xffffffffu, mx1, 2));

        float mn0 = fmaxf(m0, mx0), mn1 = fmaxf(m1, mx1);
        float corr0 = __expf(m0 - mn0), corr1 = __expf(m1 - mn1);
        float sum0 = 0.f, sum1 = 0.f;
        #pragma unroll
        for (int nt = 0; nt < 8; nt++) {
            s[nt][0] = __expf(s[nt][0] - mn0);
            s[nt][1] = __expf(s[nt][1] - mn0);
            s[nt][2] = __expf(s[nt][2] - mn1);
            s[nt][3] = __expf(s[nt][3] - mn1);
            sum0 += s[nt][0] + s[nt][1];
            sum1 += s[nt][2] + s[nt][3];
        }
        sum0 += __shfl_xor_sync(0xffffffffu, sum0, 1);
        sum0 += __shfl_xor_sync(0xffffffffu, sum0, 2);
        sum1 += __shfl_xor_sync(0xffffffffu, sum1, 1);
        sum1 += __shfl_xor_sync(0xffffffffu, sum1, 2);

        l0 = l0 * corr0 + sum0;  m0 = mn0;
        l1 = l1 * corr1 + sum1;  m1 = mn1;

        #pragma unroll
        for (int nt = 0; nt < 8; nt++) {
            o[nt][0] *= corr0; o[nt][1] *= corr0;
            o[nt][2] *= corr1; o[nt][3] *= corr1;
            s[nt][0] = tf32r(s[nt][0]);
            s[nt][1] = tf32r(s[nt][1]);
            s[nt][2] = tf32r(s[nt][2]);
            s[nt][3] = tf32r(s[nt][3]);
        }

        // ---- O += P V : P fragments gathered from s regs via shuffles ----
        #pragma unroll
        for (int ks = 0; ks < 8; ks++) {
            uint32_t af[4];
            {
                float p0 = __shfl_sync(0xffffffffu, s[ks][0], loL);
                float p1 = __shfl_sync(0xffffffffu, s[ks][1], loL);
                float p2 = __shfl_sync(0xffffffffu, s[ks][2], loL);
                float p3 = __shfl_sync(0xffffffffu, s[ks][3], loL);
                float q0 = __shfl_sync(0xffffffffu, s[ks][0], hiL);
                float q1 = __shfl_sync(0xffffffffu, s[ks][1], hiL);
                float q2 = __shfl_sync(0xffffffffu, s[ks][2], hiL);
                float q3 = __shfl_sync(0xffffffffu, s[ks][3], hiL);
                af[0] = __float_as_uint(sel ? p1 : p0);
                af[1] = __float_as_uint(sel ? p3 : p2);
                af[2] = __float_as_uint(sel ? q1 : q0);
                af[3] = __float_as_uint(sel ? q3 : q2);
            }
            #pragma unroll
            for (int nt = 0; nt < 8; nt++) {
                uint32_t bf[2];
                const uint32_t* pb = uV + (ks * 8 + ctg) * SATT + nt * 8 + gr;
                bf[0] = pb[0];
                bf[1] = pb[4 * SATT];
                mma_tf32(o[nt], af, bf);
            }
        }
    }

    // ---- final normalize + store ----
    const float inv0 = 1.0f / l0, inv1 = 1.0f / l1;
    const int row0 = tok0 + qb * 64 + mbase + gr;
    #pragma unroll
    for (int nt = 0; nt < 8; nt++) {
        const int col = h * 64 + nt * 8 + 2 * ctg;
        *reinterpret_cast<float2*>(out + (size_t)row0 * WIDTH + col) =
            make_float2(tf32r(o[nt][0] * inv0), tf32r(o[nt][1] * inv0));
        *reinterpret_cast<float2*>(out + (size_t)(row0 + 8) * WIDTH + col) =
            make_float2(tf32r(o[nt][2] * inv1), tf32r(o[nt][3] * inv1));
    }
}

// ---------------------------------------------------------------------------
// Launch
// ---------------------------------------------------------------------------
extern "C" void kernel_launch(void* const* d_in, const int* in_sizes, int n_in,
                              void* d_out, int out_size) {
    const float* x      = (const float*)d_in[0];
    const float* ln1_g  = (const float*)d_in[1];
    const float* ln1_b  = (const float*)d_in[2];
    const float* w_qkv  = (const float*)d_in[3];
    const float* w_proj = (const float*)d_in[4];
    const float* b_proj = (const float*)d_in[5];
    const float* ln2_g  = (const float*)d_in[6];
    const float* ln2_b  = (const float*)d_in[7];
    const float* w_fc1  = (const float*)d_in[8];
    const float* b_fc1  = (const float*)d_in[9];
    const float* w_fc2  = (const float*)d_in[10];
    const float* b_fc2  = (const float*)d_in[11];
    float* out = (float*)d_out;

    void *ph, *pqkv, *pattn, *px1, *pfc1, *pwq, *pwp, *pw1, *pw2;
    cudaGetSymbolAddress(&ph,    g_h);
    cudaGetSymbolAddress(&pqkv,  g_qkv);
    cudaGetSymbolAddress(&pattn, g_attn);
    cudaGetSymbolAddress(&px1,   g_x1);
    cudaGetSymbolAddress(&pfc1,  g_fc1);
    cudaGetSymbolAddress(&pwq,   g_wqkv_r);
    cudaGetSymbolAddress(&pwp,   g_wproj_r);
    cudaGetSymbolAddress(&pw1,   g_wfc1_r);
    cudaGetSymbolAddress(&pw2,   g_wfc2_r);
    float* hbuf  = (float*)ph;
    float* qkvb  = (float*)pqkv;
    float* attnb = (float*)pattn;
    float* x1b   = (float*)px1;
    float* fc1b  = (float*)pfc1;
    float* wqr   = (float*)pwq;
    float* wpr   = (float*)pwp;
    float* w1r   = (float*)pw1;
    float* w2r   = (float*)pw2;

    cudaFuncSetAttribute(gemm_tc<0,1>, cudaFuncAttributeMaxDynamicSharedMemorySize, GEMM_SMEM_BYTES);
    cudaFuncSetAttribute(gemm_tc<1,0>, cudaFuncAttributeMaxDynamicSharedMemorySize, GEMM_SMEM_BYTES);
    cudaFuncSetAttribute(gemm_tc<2,1>, cudaFuncAttributeMaxDynamicSharedMemorySize, GEMM_SMEM_BYTES);
    cudaFuncSetAttribute(attn_tc,      cudaFuncAttributeMaxDynamicSharedMemorySize, ATTN_SMEM_BYTES);

    // 0) round all weights  [index 0]
    round_all_kernel<<<SEG3 / 1024, 256>>>(w_qkv, w_proj, w_fc1, w_fc2,
                                           wqr, wpr, w1r, w2r);

    // 1) LN1  [index 1]
    ln_kernel<<<MTOK, 256>>>(x, ln1_g, ln1_b, hbuf);

    // 2) qkv = h @ w_qkv (rounded output)  [index 2]
    {
        dim3 grid(3 * WIDTH / 128, MTOK / 128);
        gemm_tc<0,1><<<grid, 256, GEMM_SMEM_BYTES>>>(MTOK, 3 * WIDTH, WIDTH,
                                                     hbuf, wqr, nullptr, nullptr, qkvb);
    }

    // 3) attention  [index 3 — ncu target, A/B vs R12's 311us / R14's 322us]
    {
        dim3 grid(SEQ / 64, 2 * HEADS);
        attn_tc<<<grid, 128, ATTN_SMEM_BYTES>>>(qkvb, attnb);
    }

    // 4) x1 = x + attn @ w_proj + b_proj
    {
        dim3 grid(WIDTH / 128, MTOK / 128);
        gemm_tc<1,0><<<grid, 256, GEMM_SMEM_BYTES>>>(MTOK, WIDTH, WIDTH,
                                                     attnb, wpr, b_proj, x, x1b);
    }

    // 5) LN2
    ln_kernel<<<MTOK, 256>>>(x1b, ln2_g, ln2_b, hbuf);

    // 6) fc1 = gelu(h @ w_fc1 + b_fc1) (rounded output)
    {
        dim3 grid(HIDDEN / 128, MTOK / 128);
        gemm_tc<2,1><<<grid, 256, GEMM_SMEM_BYTES>>>(MTOK, HIDDEN, WIDTH,
                                                     hbuf, w1r, b_fc1, nullptr, fc1b);
    }

    // 7) out = x1 + fc1 @ w_fc2 + b_fc2
    {
        dim3 grid(WIDTH / 128, MTOK / 128);
        gemm_tc<1,0><<<grid, 256, GEMM_SMEM_BYTES>>>(MTOK, WIDTH, HIDDEN,
                                                     fc1b, w2r, b_fc2, x1b, out);
    }
}

// round 16
// speedup vs baseline: 1.0387x; 1.0387x over previous
#include <cuda_runtime.h>
#include <cuda_bf16.h>
#include <math.h>
#include <stdint.h>

#define MTOK   4096
#define WIDTH  1024
#define HEADS  16
#define HDIM   64
#define HIDDEN 4096
#define SEQ    2048

__device__ float g_h   [MTOK * WIDTH];
__device__ float g_qkv [MTOK * 3 * WIDTH];
__device__ float g_attn[MTOK * WIDTH];
__device__ float g_x1  [MTOK * WIDTH];
__device__ float g_fc1 [MTOK * HIDDEN];
__device__ float g_wqkv_r [WIDTH * 3 * WIDTH];
__device__ float g_wproj_r[WIDTH * WIDTH];
__device__ float g_wfc1_r [WIDTH * HIDDEN];
__device__ float g_wfc2_r [HIDDEN * WIDTH];

__device__ __forceinline__ float warp_sum(float v) {
    #pragma unroll
    for (int o = 16; o > 0; o >>= 1) v += __shfl_xor_sync(0xffffffffu, v, o);
    return v;
}

__device__ __forceinline__ float tf32r(float x) {
    uint32_t u;
    asm("cvt.rna.tf32.f32 %0, %1;" : "=r"(u) : "f"(x));
    return __uint_as_float(u);
}

__device__ __forceinline__ void mma_tf32(float c[4], const uint32_t a[4], const uint32_t b[2]) {
    asm volatile(
        "mma.sync.aligned.m16n8k8.row.col.f32.tf32.tf32.f32 "
        "{%0,%1,%2,%3}, {%4,%5,%6,%7}, {%8,%9}, {%0,%1,%2,%3};\n"
        : "+f"(c[0]), "+f"(c[1]), "+f"(c[2]), "+f"(c[3])
        : "r"(a[0]), "r"(a[1]), "r"(a[2]), "r"(a[3]),
          "r"(b[0]), "r"(b[1]));
}

__device__ __forceinline__ void cp_async16(uint32_t s, const void* g) {
    asm volatile("cp.async.cg.shared.global [%0], [%1], 16;\n" :: "r"(s), "l"(g));
}
__device__ __forceinline__ void cp_commit() {
    asm volatile("cp.async.commit_group;\n" ::: "memory");
}
template <int N>
__device__ __forceinline__ void cp_wait() {
    asm volatile("cp.async.wait_group %0;\n" :: "n"(N) : "memory");
}

__device__ __forceinline__ float gelu_exact(float x) {
    return 0.5f * x * (1.0f + erff(x * 0.7071067811865476f));
}

// ---------------------------------------------------------------------------
// Merged weight rounding
// ---------------------------------------------------------------------------
#define SEG0 786432
#define SEG1 1048576
#define SEG2 2097152
#define SEG3 3145728

__global__ void round_all_kernel(const float* __restrict__ wqkv,
                                 const float* __restrict__ wproj,
                                 const float* __restrict__ wfc1,
                                 const float* __restrict__ wfc2,
                                 float* __restrict__ oqkv,
                                 float* __restrict__ oproj,
                                 float* __restrict__ ofc1,
                                 float* __restrict__ ofc2) {
    int blk0 = blockIdx.x * 1024;
    const float4* in;
    float4* out;
    int off;
    if (blk0 < SEG0)      { in = (const float4*)wqkv;  out = (float4*)oqkv;  off = 0;    }
    else if (blk0 < SEG1) { in = (const float4*)wproj; out = (float4*)oproj; off = SEG0; }
    else if (blk0 < SEG2) { in = (const float4*)wfc1;  out = (float4*)ofc1;  off = SEG1; }
    else                  { in = (const float4*)wfc2;  out = (float4*)ofc2;  off = SEG2; }
    int base = blk0 - off + threadIdx.x;
    #pragma unroll
    for (int i = 0; i < 4; i++) {
        int idx = base + i * 256;
        float4 v = in[idx];
        out[idx] = make_float4(tf32r(v.x), tf32r(v.y), tf32r(v.z), tf32r(v.w));
    }
}

__global__ void ln_kernel(const float* __restrict__ x,
                          const float* __restrict__ g,
                          const float* __restrict__ b,
                          float* __restrict__ out) {
    int row = blockIdx.x;
    int t   = threadIdx.x;
    const float4* xr = reinterpret_cast<const float4*>(x + (size_t)row * WIDTH);
    float4 v = xr[t];
    float s  = v.x + v.y + v.z + v.w;
    float ss = v.x*v.x + v.y*v.y + v.z*v.z + v.w*v.w;

    __shared__ float red_s[8], red_ss[8];
    float ws = warp_sum(s), wss = warp_sum(ss);
    int wid = t >> 5, lid = t & 31;
    if (lid == 0) { red_s[wid] = ws; red_ss[wid] = wss; }
    __syncthreads();
    if (wid == 0) {
        float a  = (lid < 8) ? red_s[lid]  : 0.f;
        float a2 = (lid < 8) ? red_ss[lid] : 0.f;
        a  = warp_sum(a);
        a2 = warp_sum(a2);
        if (lid == 0) { red_s[0] = a; red_ss[0] = a2; }
    }
    __syncthreads();
    float mu  = red_s[0]  * (1.0f / WIDTH);
    float var = red_ss[0] * (1.0f / WIDTH) - mu * mu;
    float rs  = rsqrtf(var + 1e-5f);

    const float4* g4 = reinterpret_cast<const float4*>(g);
    const float4* b4 = reinterpret_cast<const float4*>(b);
    float4 gg = g4[t], bb = b4[t];
    float4 o;
    o.x = tf32r((v.x - mu) * rs * gg.x + bb.x);
    o.y = tf32r((v.y - mu) * rs * gg.y + bb.y);
    o.z = tf32r((v.z - mu) * rs * gg.z + bb.z);
    o.w = tf32r((v.w - mu) * rs * gg.w + bb.w);
    reinterpret_cast<float4*>(out + (size_t)row * WIDTH)[t] = o;
}

// ---------------------------------------------------------------------------
// TF32 tensor-core GEMM (proven R4/R9 config)
// ---------------------------------------------------------------------------
#define SA 36
#define SB 136
#define AS_FLOATS (128 * SA)
#define BS_FLOATS (32 * SB)
#define STAGE_FLOATS (AS_FLOATS + BS_FLOATS)
#define NSTAGE 3
#define GEMM_SMEM_BYTES (NSTAGE * STAGE_FLOATS * 4)

template <int OP, int ROUND_OUT>
__global__ void __launch_bounds__(256, 2)
gemm_tc(int M, int N, int K,
        const float* __restrict__ A,
        const float* __restrict__ B,
        const float* __restrict__ bias,
        const float* __restrict__ res,
        float* __restrict__ C) {
    extern __shared__ float sm[];

    const int tid     = threadIdx.x;
    const int warpId  = tid >> 5;
    const int lane    = tid & 31;
    const int gr      = lane >> 2;
    const int ctg     = lane & 3;
    const int warpRow = warpId >> 2;
    const int warpCol = warpId & 3;

    const int cRow = blockIdx.y;
    const int cCol = blockIdx.x;

    const float* Ablk = A + (size_t)cRow * 128 * K;
    const float* Bblk = B + cCol * 128;

    const uint32_t smBase = (uint32_t)__cvta_generic_to_shared(sm);

    auto load_stage = [&](int stg, int kb) {
        const uint32_t stageA = smBase + (uint32_t)(stg * STAGE_FLOATS) * 4u;
        const uint32_t stageB = stageA + (uint32_t)AS_FLOATS * 4u;
        const int kOff = kb << 5;
        #pragma unroll
        for (int i = 0; i < 4; i++) {
            int aIdx = tid + i * 256;
            int ar = aIdx >> 3, ac = (aIdx & 7) << 2;
            cp_async16(stageA + (uint32_t)(ar * SA + ac) * 4u,
                       Ablk + (size_t)ar * K + kOff + ac);
            int bIdx = tid + i * 256;
            int br = bIdx >> 5, bc = (bIdx & 31) << 2;
            cp_async16(stageB + (uint32_t)(br * SB + bc) * 4u,
                       Bblk + (size_t)(kOff + br) * N + bc);
        }
    };

    float acc[4][4][4];
    #pragma unroll
    for (int i = 0; i < 4; i++)
        #pragma unroll
        for (int j = 0; j < 4; j++)
            #pragma unroll
            for (int k = 0; k < 4; k++) acc[i][j][k] = 0.f;

    const int nChunk = K >> 5;

    load_stage(0, 0); cp_commit();
    load_stage(1, 1); cp_commit();
    cp_wait<1>();
    __syncthreads();

    for (int kb = 0; kb < nChunk; kb++) {
        const int cur = kb % NSTAGE;
        if (kb + 2 < nChunk) load_stage((kb + 2) % NSTAGE, kb + 2);
        cp_commit();

        const uint32_t* uAs = reinterpret_cast<const uint32_t*>(sm + cur * STAGE_FLOATS);
        const uint32_t* uBs = uAs + AS_FLOATS;

        #pragma unroll
        for (int ks = 0; ks < 4; ks++) {
            uint32_t af[4][4];
            #pragma unroll
            for (int mt = 0; mt < 4; mt++) {
                int m0 = warpRow * 64 + mt * 16 + gr;
                const uint32_t* pa = uAs + m0 * SA + ks * 8 + ctg;
                af[mt][0] = pa[0];
                af[mt][1] = pa[8 * SA];
                af[mt][2] = pa[4];
                af[mt][3] = pa[8 * SA + 4];
            }
            uint32_t bf[4][2];
            #pragma unroll
            for (int nt = 0; nt < 4; nt++) {
                int nb = warpCol * 32 + nt * 8 + gr;
                const uint32_t* pb = uBs + (ks * 8 + ctg) * SB + nb;
                bf[nt][0] = pb[0];
                bf[nt][1] = pb[4 * SB];
            }
            #pragma unroll
            for (int mt = 0; mt < 4; mt++)
                #pragma unroll
                for (int nt = 0; nt < 4; nt++)
                    mma_tf32(acc[mt][nt], af[mt], bf[nt]);
        }

        cp_wait<1>();
        __syncthreads();
    }

    #pragma unroll
    for (int mt = 0; mt < 4; mt++) {
        #pragma unroll
        for (int rr = 0; rr < 2; rr++) {
            const int row = cRow * 128 + warpRow * 64 + mt * 16 + gr + rr * 8;
            #pragma unroll
            for (int nt = 0; nt < 4; nt++) {
                const int col = cCol * 128 + warpCol * 32 + nt * 8 + 2 * ctg;
                float v0 = acc[mt][nt][rr * 2 + 0];
                float v1 = acc[mt][nt][rr * 2 + 1];
                if (OP == 1) {
                    float2 bi = *reinterpret_cast<const float2*>(bias + col);
                    float2 rv = *reinterpret_cast<const float2*>(res + (size_t)row * N + col);
                    v0 += bi.x + rv.x;
                    v1 += bi.y + rv.y;
                } else if (OP == 2) {
                    float2 bi = *reinterpret_cast<const float2*>(bias + col);
                    v0 = gelu_exact(v0 + bi.x);
                    v1 = gelu_exact(v1 + bi.y);
                }
                if (ROUND_OUT) { v0 = tf32r(v0); v1 = tf32r(v1); }
                *reinterpret_cast<float2*>(C + (size_t)row * N + col) = make_float2(v0, v1);
            }
        }
    }
}

// ---------------------------------------------------------------------------
// Flash attention: R12 structure (BQ=128, 4 warps x 32 query rows, Ps P-path)
// + double-buffered cp.async K/V tiles to hide global load latency.
// smem: 2 stages x (Ks+Vs) + Ps = 104448 bytes; 2 CTAs/SM still fit.
// ---------------------------------------------------------------------------
#define SATT 68
#define KV_TILE (64 * SATT)            // 4352 floats
#define STAGE_ATT (2 * KV_TILE)        // Ks+Vs per stage
#define P_TILE (128 * SATT)
#define ATTN_SMEM_BYTES ((2 * STAGE_ATT + P_TILE) * 4)   // 104448

__global__ void __launch_bounds__(128)
attn_tc(const float* __restrict__ qkv, float* __restrict__ out) {
    extern __shared__ float sm[];
    float* Ps = sm + 2 * STAGE_ATT;
    const uint32_t* uP = reinterpret_cast<const uint32_t*>(Ps);
    const uint32_t smBase = (uint32_t)__cvta_generic_to_shared(sm);

    const int t     = threadIdx.x;
    const int warp  = t >> 5;
    const int lane  = t & 31;
    const int gr    = lane >> 2;
    const int ctg   = lane & 3;
    const int mbase = warp * 32;

    const int qb = blockIdx.x;
    const int bh = blockIdx.y;
    const int bb = bh >> 4;
    const int h  = bh & 15;
    const int tok0 = bb * SEQ;

    auto load_kv = [&](int stg, int kb) {
        const uint32_t base = smBase + (uint32_t)(stg * STAGE_ATT) * 4u;
        #pragma unroll
        for (int i = 0; i < 8; i++) {
            int idx = t + i * 128;
            int row = idx >> 4;
            int c   = (idx & 15) << 2;
            const float* src = qkv + (size_t)(tok0 + kb * 64 + row) * 3072 + h * 64 + c;
            cp_async16(base + (uint32_t)(row * SATT + c) * 4u,              src + 1024);
            cp_async16(base + (uint32_t)(KV_TILE + row * SATT + c) * 4u,   src + 2048);
        }
    };

    // prologue: start fetching K/V tile 0 while Q stages through Ps
    load_kv(0, 0); cp_commit();

    #pragma unroll
    for (int i = 0; i < 16; i++) {
        int idx = t + i * 128;
        int row = idx >> 4;
        int c   = (idx & 15) << 2;
        *reinterpret_cast<float4*>(&Ps[row * SATT + c]) =
            *reinterpret_cast<const float4*>(
                qkv + (size_t)(tok0 + qb * 128 + row) * 3072 + h * 64 + c);
    }
    __syncthreads();
    uint32_t qf[2][8][4];
    #pragma unroll
    for (int mt = 0; mt < 2; mt++)
        #pragma unroll
        for (int ks = 0; ks < 8; ks++) {
            const uint32_t* pq = uP + (mbase + mt * 16 + gr) * SATT + ks * 8 + ctg;
            qf[mt][ks][0] = pq[0];
            qf[mt][ks][1] = pq[8 * SATT];
            qf[mt][ks][2] = pq[4];
            qf[mt][ks][3] = pq[8 * SATT + 4];
        }
    // (P stores are warp-private rows, and each warp extracts before storing:
    //  no cross-warp hazard on Ps — same reasoning as R12.)

    float mM[2][2], lL[2][2];
    #pragma unroll
    for (int mt = 0; mt < 2; mt++) { mM[mt][0] = -1e30f; mM[mt][1] = -1e30f;
                                     lL[mt][0] = 0.f;    lL[mt][1] = 0.f; }
    float o[2][8][4];
    #pragma unroll
    for (int mt = 0; mt < 2; mt++)
        #pragma unroll
        for (int nt = 0; nt < 8; nt++)
            #pragma unroll
            for (int k = 0; k < 4; k++) o[mt][nt][k] = 0.f;

    for (int kb = 0; kb < SEQ / 64; kb++) {
        const int cur = kb & 1;
        if (kb + 1 < SEQ / 64) load_kv(cur ^ 1, kb + 1);
        cp_commit();
        cp_wait<1>();          // stage cur's group complete
        __syncthreads();       // publish stage cur to all warps

        const uint32_t* uK = reinterpret_cast<const uint32_t*>(sm + cur * STAGE_ATT);
        const uint32_t* uV = uK + KV_TILE;

        // ---- S = Q K^T (both m-tiles share each K fragment) ----
        float s[2][8][4];
        #pragma unroll
        for (int mt = 0; mt < 2; mt++)
            #pragma unroll
            for (int nt = 0; nt < 8; nt++)
                #pragma unroll
                for (int k = 0; k < 4; k++) s[mt][nt][k] = 0.f;

        #pragma unroll
        for (int ks = 0; ks < 8; ks++) {
            #pragma unroll
            for (int nt = 0; nt < 8; nt++) {
                uint32_t bf[2];
                const uint32_t* pb = uK + (nt * 8 + gr) * SATT + ks * 8 + ctg;
                bf[0] = pb[0];
                bf[1] = pb[4];
                mma_tf32(s[0][nt], qf[0][ks], bf);
                mma_tf32(s[1][nt], qf[1][ks], bf);
            }
        }

        // ---- online softmax per m-tile ----
        #pragma unroll
        for (int mt = 0; mt < 2; mt++) {
            float mx0 = -1e30f, mx1 = -1e30f;
            #pragma unroll
            for (int nt = 0; nt < 8; nt++) {
                s[mt][nt][0] *= 0.125f; s[mt][nt][1] *= 0.125f;
                s[mt][nt][2] *= 0.125f; s[mt][nt][3] *= 0.125f;
                mx0 = fmaxf(mx0, fmaxf(s[mt][nt][0], s[mt][nt][1]));
                mx1 = fmaxf(mx1, fmaxf(s[mt][nt][2], s[mt][nt][3]));
            }
            mx0 = fmaxf(mx0, __shfl_xor_sync(0xffffffffu, mx0, 1));
            mx0 = fmaxf(mx0, __shfl_xor_sync(0xffffffffu, mx0, 2));
            mx1 = fmaxf(mx1, __shfl_xor_sync(0xffffffffu, mx1, 1));
            mx1 = fmaxf(mx1, __shfl_xor_sync(0xffffffffu, mx1, 2));

            float mn0 = fmaxf(mM[mt][0], mx0), mn1 = fmaxf(mM[mt][1], mx1);
            float corr0 = __expf(mM[mt][0] - mn0), corr1 = __expf(mM[mt][1] - mn1);
            float sum0 = 0.f, sum1 = 0.f;
            #pragma unroll
            for (int nt = 0; nt < 8; nt++) {
                s[mt][nt][0] = __expf(s[mt][nt][0] - mn0);
                s[mt][nt][1] = __expf(s[mt][nt][1] - mn0);
                s[mt][nt][2] = __expf(s[mt][nt][2] - mn1);
                s[mt][nt][3] = __expf(s[mt][nt][3] - mn1);
                sum0 += s[mt][nt][0] + s[mt][nt][1];
                sum1 += s[mt][nt][2] + s[mt][nt][3];
            }
            sum0 += __shfl_xor_sync(0xffffffffu, sum0, 1);
            sum0 += __shfl_xor_sync(0xffffffffu, sum0, 2);
            sum1 += __shfl_xor_sync(0xffffffffu, sum1, 1);
            sum1 += __shfl_xor_sync(0xffffffffu, sum1, 2);

            lL[mt][0] = lL[mt][0] * corr0 + sum0;  mM[mt][0] = mn0;
            lL[mt][1] = lL[mt][1] * corr1 + sum1;  mM[mt][1] = mn1;

            #pragma unroll
            for (int nt = 0; nt < 8; nt++) {
                o[mt][nt][0] *= corr0; o[mt][nt][1] *= corr0;
                o[mt][nt][2] *= corr1; o[mt][nt][3] *= corr1;
            }

            // store P rows for this m-tile (warp-private)
            #pragma unroll
            for (int nt = 0; nt < 8; nt++) {
                *reinterpret_cast<float2*>(
                    &Ps[(mbase + mt * 16 + gr) * SATT + nt * 8 + 2 * ctg]) =
                    make_float2(tf32r(s[mt][nt][0]), tf32r(s[mt][nt][1]));
                *reinterpret_cast<float2*>(
                    &Ps[(mbase + mt * 16 + gr + 8) * SATT + nt * 8 + 2 * ctg]) =
                    make_float2(tf32r(s[mt][nt][2]), tf32r(s[mt][nt][3]));
            }
        }
        __syncwarp();

        // ---- O += P V : each bf feeds both m-tiles ----
        #pragma unroll
        for (int ks = 0; ks < 8; ks++) {
            uint32_t af0[4], af1[4];
            const uint32_t* pa0 = uP + (mbase + gr) * SATT + ks * 8 + ctg;
            af0[0] = pa0[0];
            af0[1] = pa0[8 * SATT];
            af0[2] = pa0[4];
            af0[3] = pa0[8 * SATT + 4];
            const uint32_t* pa1 = uP + (mbase + 16 + gr) * SATT + ks * 8 + ctg;
            af1[0] = pa1[0];
            af1[1] = pa1[8 * SATT];
            af1[2] = pa1[4];
            af1[3] = pa1[8 * SATT + 4];
            #pragma unroll
            for (int nt = 0; nt < 8; nt++) {
                uint32_t bf[2];
                const uint32_t* pb = uV + (ks * 8 + ctg) * SATT + nt * 8 + gr;
                bf[0] = pb[0];
                bf[1] = pb[4 * SATT];
                mma_tf32(o[0][nt], af0, bf);
                mma_tf32(o[1][nt], af1, bf);
            }
        }

        __syncthreads();   // stage cur fully consumed before kb+1 overwrites it
    }

    // ---- final normalize + store ----
    #pragma unroll
    for (int mt = 0; mt < 2; mt++) {
        const float inv0 = 1.0f / lL[mt][0], inv1 = 1.0f / lL[mt][1];
        const int row0 = tok0 + qb * 128 + mbase + mt * 16 + gr;
        #pragma unroll
        for (int nt = 0; nt < 8; nt++) {
            const int col = h * 64 + nt * 8 + 2 * ctg;
            *reinterpret_cast<float2*>(out + (size_t)row0 * WIDTH + col) =
                make_float2(tf32r(o[mt][nt][0] * inv0), tf32r(o[mt][nt][1] * inv0));
            *reinterpret_cast<float2*>(out + (size_t)(row0 + 8) * WIDTH + col) =
                make_float2(tf32r(o[mt][nt][2] * inv1), tf32r(o[mt][nt][3] * inv1));
        }
    }
}

// ---------------------------------------------------------------------------
// Launch
// ---------------------------------------------------------------------------
extern "C" void kernel_launch(void* const* d_in, const int* in_sizes, int n_in,
                              void* d_out, int out_size) {
    const float* x      = (const float*)d_in[0];
    const float* ln1_g  = (const float*)d_in[1];
    const float* ln1_b  = (const float*)d_in[2];
    const float* w_qkv  = (const float*)d_in[3];
    const float* w_proj = (const float*)d_in[4];
    const float* b_proj = (const float*)d_in[5];
    const float* ln2_g  = (const float*)d_in[6];
    const float* ln2_b  = (const float*)d_in[7];
    const float* w_fc1  = (const float*)d_in[8];
    const float* b_fc1  = (const float*)d_in[9];
    const float* w_fc2  = (const float*)d_in[10];
    const float* b_fc2  = (const float*)d_in[11];
    float* out = (float*)d_out;

    void *ph, *pqkv, *pattn, *px1, *pfc1, *pwq, *pwp, *pw1, *pw2;
    cudaGetSymbolAddress(&ph,    g_h);
    cudaGetSymbolAddress(&pqkv,  g_qkv);
    cudaGetSymbolAddress(&pattn, g_attn);
    cudaGetSymbolAddress(&px1,   g_x1);
    cudaGetSymbolAddress(&pfc1,  g_fc1);
    cudaGetSymbolAddress(&pwq,   g_wqkv_r);
    cudaGetSymbolAddress(&pwp,   g_wproj_r);
    cudaGetSymbolAddress(&pw1,   g_wfc1_r);
    cudaGetSymbolAddress(&pw2,   g_wfc2_r);
    float* hbuf  = (float*)ph;
    float* qkvb  = (float*)pqkv;
    float* attnb = (float*)pattn;
    float* x1b   = (float*)px1;
    float* fc1b  = (float*)pfc1;
    float* wqr   = (float*)pwq;
    float* wpr   = (float*)pwp;
    float* w1r   = (float*)pw1;
    float* w2r   = (float*)pw2;

    cudaFuncSetAttribute(gemm_tc<0,1>, cudaFuncAttributeMaxDynamicSharedMemorySize, GEMM_SMEM_BYTES);
    cudaFuncSetAttribute(gemm_tc<1,0>, cudaFuncAttributeMaxDynamicSharedMemorySize, GEMM_SMEM_BYTES);
    cudaFuncSetAttribute(gemm_tc<2,1>, cudaFuncAttributeMaxDynamicSharedMemorySize, GEMM_SMEM_BYTES);
    cudaFuncSetAttribute(attn_tc,      cudaFuncAttributeMaxDynamicSharedMemorySize, ATTN_SMEM_BYTES);

    // 0) round all weights  [index 0]
    round_all_kernel<<<SEG3 / 1024, 256>>>(w_qkv, w_proj, w_fc1, w_fc2,
                                           wqr, wpr, w1r, w2r);

    // 1) LN1  [index 1]
    ln_kernel<<<MTOK, 256>>>(x, ln1_g, ln1_b, hbuf);

    // 2) qkv = h @ w_qkv (rounded output)  [index 2]
    {
        dim3 grid(3 * WIDTH / 128, MTOK / 128);
        gemm_tc<0,1><<<grid, 256, GEMM_SMEM_BYTES>>>(MTOK, 3 * WIDTH, WIDTH,
                                                     hbuf, wqr, nullptr, nullptr, qkvb);
    }

    // 3) attention  [index 3 — ncu target, A/B vs R12's 311us]
    {
        dim3 grid(SEQ / 128, 2 * HEADS);
        attn_tc<<<grid, 128, ATTN_SMEM_BYTES>>>(qkvb, attnb);
    }

    // 4) x1 = x + attn @ w_proj + b_proj
    {
        dim3 grid(WIDTH / 128, MTOK / 128);
        gemm_tc<1,0><<<grid, 256, GEMM_SMEM_BYTES>>>(MTOK, WIDTH, WIDTH,
                                                     attnb, wpr, b_proj, x, x1b);
    }

    // 5) LN2
    ln_kernel<<<MTOK, 256>>>(x1b, ln2_g, ln2_b, hbuf);

    // 6) fc1 = gelu(h @ w_fc1 + b_fc1) (rounded output)
    {
        dim3 grid(HIDDEN / 128, MTOK / 128);
        gemm_tc<2,1><<<grid, 256, GEMM_SMEM_BYTES>>>(MTOK, HIDDEN, WIDTH,
                                                     hbuf, w1r, b_fc1, nullptr, fc1b);
    }

    // 7) out = x1 + fc1 @ w_fc2 + b_fc2
    {
        dim3 grid(WIDTH / 128, MTOK / 128);
        gemm_tc<1,0><<<grid, 256, GEMM_SMEM_BYTES>>>(MTOK, WIDTH, HIDDEN,
                                                     fc1b, w2r, b_fc2, x1b, out);
    }
}